// round 4
// baseline (speedup 1.0000x reference)
#include <cuda_runtime.h>
#include <cuda_bf16.h>

#define V_DIM 32
#define NB 14          // N_BASIS
#define NP 496         // V*(V-1)/2
#define NW 16          // warps per block
#define NTHREADS 512
#define GRID 444       // 3 blocks/SM on 148 SMs

struct WarpScratch {
    float  xs[V_DIM];      // raw input row
    float4 Bs4[V_DIM];     // basis quadruple per column (only 0..30 used)
    int    PT[V_DIM];      // per-column params row base = j0*NP
    float  Ls[NP];         // lam values, p-linear (conflict-free)
    float  Od[V_DIM];      // per-row out staging
};

struct SmemLayout {
    float P[NB * NP];      // staged params (27776 B)
    WarpScratch w[NW];
    float red[3][NW];
};

__global__ __launch_bounds__(NTHREADS, 3)
void decor_kernel(const float* __restrict__ input,
                  const float* __restrict__ params,
                  float* __restrict__ d_out,
                  float* __restrict__ scal,
                  int n)
{
    extern __shared__ char smem_raw[];
    SmemLayout* S = reinterpret_cast<SmemLayout*>(smem_raw);

    const int tid  = threadIdx.x;
    const int warp = tid >> 5;
    const int lane = tid & 31;

    // ---- stage params once per block ----
    for (int i = tid; i < NB * NP; i += NTHREADS) S->P[i] = params[i];

    WarpScratch* W = &S->w[warp];

    // row-independent pair geometry: for p = lane+32*i, A[i] = v*32 - v(v-1)/2
    // so (A[i] + p) gives idx = v*32 + c
    int A[16];
    {
        #pragma unroll
        for (int i = 0; i < 16; i++) {
            int p = lane + 32 * i;
            int v = (int)((1.0f + sqrtf(8.0f * (float)p + 1.0f)) * 0.5f);
            while (v * (v + 1) / 2 <= p) v++;
            while (v * (v - 1) / 2 > p) v--;
            A[i] = v * 32 - v * (v - 1) / 2;
        }
    }
    __syncthreads();

    // ---- block 0: fused penalties from smem-staged params ----
    if (blockIdx.x == 0) {
        float s0 = 0.f, s1 = 0.f, s2 = 0.f;
        for (int i = tid; i < NB * NP; i += NTHREADS) {
            float p0 = S->P[i];
            s0 += p0 * p0;
            int k = i / NP;
            if (k < NB - 1) {
                float p1 = S->P[i + NP];
                float a = p1 - p0;
                s1 += a * a;
                if (k < NB - 2) {
                    float b = S->P[i + 2 * NP] - 2.0f * p1 + p0;
                    s2 += b * b;
                }
            }
        }
        #pragma unroll
        for (int off = 16; off > 0; off >>= 1) {
            s0 += __shfl_down_sync(0xffffffffu, s0, off);
            s1 += __shfl_down_sync(0xffffffffu, s1, off);
            s2 += __shfl_down_sync(0xffffffffu, s2, off);
        }
        if (lane == 0) { S->red[0][warp] = s2; S->red[1][warp] = s1; S->red[2][warp] = s0; }
        __syncthreads();
        if (tid < 3) {
            float t = 0.f;
            #pragma unroll
            for (int w2 = 0; w2 < NW; w2++) t += S->red[tid][w2];
            scal[tid] = t;   // [0]=second, [1]=first, [2]=param
        }
    }

    const float LOv = -15.0f, HIv = 15.0f;
    const float inv_dist = 11.0f / 30.0f;

    float* lm = d_out + (size_t)n * V_DIM;
    const int row_stride = gridDim.x * NW;

    for (int row = blockIdx.x * NW + warp; row < n; row += row_stride) {

        // load input row (coalesced)
        float xi = input[(size_t)row * V_DIM + lane];
        W->xs[lane] = xi;

        // cubic uniform B-spline: 4 nonzero funcs, closed form
        if (lane < 31) {
            float xc = fminf(fmaxf(xi, LOv), HIv - 1e-6f);
            float s  = (xc - LOv) * inv_dist;       // in [0, 11)
            int j0 = (int)s;
            j0 = min(j0, 10);
            float u  = s - (float)j0;
            float um = 1.0f - u;
            float u2 = u * u, u3 = u2 * u;
            W->Bs4[lane] = make_float4(
                um * um * um * (1.0f / 6.0f),
                (3.0f * u3 - 6.0f * u2 + 4.0f) * (1.0f / 6.0f),
                (-3.0f * u3 + 3.0f * u2 + 3.0f * u + 1.0f) * (1.0f / 6.0f),
                u3 * (1.0f / 6.0f));
            W->PT[lane] = j0 * NP;
        }
        __syncwarp();

        // lam: p-linear layout (conflict-free STS), dense lanes
        #pragma unroll
        for (int i = 0; i < 16; i++) {
            int p = lane + 32 * i;
            if (p < NP) {
                int c = (A[i] + p) & 31;
                float4 B = W->Bs4[c];
                const float* Pp = S->P + W->PT[c] + p;
                float l = B.x * Pp[0];
                l = fmaf(B.y, Pp[NP],     l);
                l = fmaf(B.z, Pp[2 * NP], l);
                l = fmaf(B.w, Pp[3 * NP], l);
                W->Ls[p] = l;
            }
        }
        __syncwarp();

        // lm store (STG.128, coalesced) with fused out = lm @ x
        float4* lmrow = reinterpret_cast<float4*>(lm + (size_t)row * V_DIM * V_DIM);
        #pragma unroll
        for (int i = 0; i < 8; i++) {
            int t4 = lane + 32 * i;          // float4 index == v*8 + (c0/4)
            int v  = t4 >> 3;
            int c0 = (t4 & 7) << 2;
            int pb = (v * (v - 1)) >> 1;
            float vals[4];
            #pragma unroll
            for (int q = 0; q < 4; q++) {
                int c = c0 + q;
                float val = 0.0f;
                if (c < v)       val = W->Ls[pb + c];
                else if (c == v) val = 1.0f;
                vals[q] = val;
            }
            __stcs(&lmrow[t4], make_float4(vals[0], vals[1], vals[2], vals[3]));

            // dot with x for this v (8 lanes per v)
            const float4 x4 = reinterpret_cast<const float4*>(W->xs)[t4 & 7];
            float dv = vals[0] * x4.x + vals[1] * x4.y + vals[2] * x4.z + vals[3] * x4.w;
            dv += __shfl_xor_sync(0xffffffffu, dv, 4, 8);
            dv += __shfl_xor_sync(0xffffffffu, dv, 2, 8);
            dv += __shfl_xor_sync(0xffffffffu, dv, 1, 8);
            if ((lane & 7) == 0) W->Od[v] = dv;
        }
        __syncwarp();

        // one coalesced out-row store
        d_out[(size_t)row * V_DIM + lane] = W->Od[lane];

        __syncwarp();   // protect per-warp scratch before next row
    }
}

extern "C" void kernel_launch(void* const* d_in, const int* in_sizes, int n_in,
                              void* d_out, int out_size)
{
    const float* input  = (const float*)d_in[0];
    // d_in[1] = log_d (unused by the reference's outputs)
    const float* params = (const float*)d_in[2];
    float* outp = (float*)d_out;
    int n = in_sizes[0] / V_DIM;

    float* scal = outp + (size_t)n * V_DIM + (size_t)n * V_DIM * V_DIM;

    size_t smem = sizeof(SmemLayout);
    cudaFuncSetAttribute(decor_kernel, cudaFuncAttributeMaxDynamicSharedMemorySize, (int)smem);

    decor_kernel<<<GRID, NTHREADS, smem>>>(input, params, outp, scal, n);
}

// round 5
// speedup vs baseline: 1.4226x; 1.4226x over previous
#include <cuda_runtime.h>
#include <cuda_bf16.h>

#define V_DIM 32
#define NB 14          // N_BASIS
#define NP 496         // V*(V-1)/2
#define PSTRIDE 512    // padded params row stride: bank-conflict-free (512%32==0)
#define NW 16          // warps per block
#define NTHREADS 512
#define GRID 296       // 2 blocks/SM on 148 SMs

struct WarpScratch {
    float Ls[NP];          // lam values, p-linear (conflict-free STS)
    float xs[V_DIM];       // input row (float4-readable)
    float Od[V_DIM];       // out staging
};

struct SmemLayout {
    float P[NB * PSTRIDE]; // padded staged params (28672 B)
    WarpScratch w[NW];
    float red[3][NW];
};

__global__ __launch_bounds__(NTHREADS, 2)
void decor_kernel(const float* __restrict__ input,
                  const float* __restrict__ params,
                  float* __restrict__ d_out,
                  float* __restrict__ scal,
                  int n)
{
    extern __shared__ char smem_raw[];
    SmemLayout* S = reinterpret_cast<SmemLayout*>(smem_raw);

    const int tid  = threadIdx.x;
    const int warp = tid >> 5;
    const int lane = tid & 31;

    // ---- stage params (padded) once per block ----
    for (int i = tid; i < NB * NP; i += NTHREADS) {
        int r = i / NP, cc = i - r * NP;
        S->P[r * PSTRIDE + cc] = params[i];
    }

    WarpScratch* W = &S->w[warp];

    // row-independent pair geometry: p = lane+32*i -> idx = v*32+c = A[i]+p
    int A[16];
    #pragma unroll
    for (int i = 0; i < 16; i++) {
        int p = lane + 32 * i;
        int v = (int)((1.0f + sqrtf(8.0f * (float)p + 1.0f)) * 0.5f);
        while (v * (v + 1) / 2 <= p) v++;
        while (v * (v - 1) / 2 > p) v--;
        A[i] = v * 32 - v * (v - 1) / 2;
    }
    __syncthreads();

    // ---- block 0: fused penalties ----
    if (blockIdx.x == 0) {
        float s0 = 0.f, s1 = 0.f, s2 = 0.f;
        for (int i = tid; i < NB * NP; i += NTHREADS) {
            int k = i / NP, cc = i - k * NP;
            float p0 = S->P[k * PSTRIDE + cc];
            s0 += p0 * p0;
            if (k < NB - 1) {
                float p1 = S->P[(k + 1) * PSTRIDE + cc];
                float a = p1 - p0;
                s1 += a * a;
                if (k < NB - 2) {
                    float b = S->P[(k + 2) * PSTRIDE + cc] - 2.0f * p1 + p0;
                    s2 += b * b;
                }
            }
        }
        #pragma unroll
        for (int off = 16; off > 0; off >>= 1) {
            s0 += __shfl_down_sync(0xffffffffu, s0, off);
            s1 += __shfl_down_sync(0xffffffffu, s1, off);
            s2 += __shfl_down_sync(0xffffffffu, s2, off);
        }
        if (lane == 0) { S->red[0][warp] = s2; S->red[1][warp] = s1; S->red[2][warp] = s0; }
        __syncthreads();
        if (tid < 3) {
            float t = 0.f;
            #pragma unroll
            for (int w2 = 0; w2 < NW; w2++) t += S->red[tid][w2];
            scal[tid] = t;   // [0]=second, [1]=first, [2]=param
        }
    }

    const float LOv = -15.0f, HIv = 15.0f;
    const float inv_dist = 11.0f / 30.0f;

    float* lm = d_out + (size_t)n * V_DIM;
    const int row_stride = gridDim.x * NW;

    for (int row = blockIdx.x * NW + warp; row < n; row += row_stride) {

        // input row: lane owns column `lane` (coalesced LDG)
        float xi = input[(size_t)row * V_DIM + lane];
        W->xs[lane] = xi;

        // basis for column c = lane, entirely in registers (no smem)
        float b0 = 0.f, b1 = 0.f, b2 = 0.f, b3 = 0.f;
        int   pt = 0;
        {
            float xc = fminf(fmaxf(xi, LOv), HIv - 1e-6f);
            float s  = (xc - LOv) * inv_dist;       // [0, 11)
            int j0 = min((int)s, 10);
            float u  = s - (float)j0;
            float um = 1.0f - u;
            float u2 = u * u, u3 = u2 * u;
            b0 = um * um * um * (1.0f / 6.0f);
            b1 = (3.0f * u3 - 6.0f * u2 + 4.0f) * (1.0f / 6.0f);
            b2 = (-3.0f * u3 + 3.0f * u2 + 3.0f * u + 1.0f) * (1.0f / 6.0f);
            b3 = u3 * (1.0f / 6.0f);
            pt = j0 * PSTRIDE;
        }
        __syncwarp();

        // lam: basis via shuffle (no crossbar), P conflict-free, Ls p-linear
        #pragma unroll
        for (int i = 0; i < 16; i++) {
            int p = lane + 32 * i;
            int c = (A[i] + p) & 31;
            float c0 = __shfl_sync(0xffffffffu, b0, c);
            float c1 = __shfl_sync(0xffffffffu, b1, c);
            float c2 = __shfl_sync(0xffffffffu, b2, c);
            float c3 = __shfl_sync(0xffffffffu, b3, c);
            int   cp = __shfl_sync(0xffffffffu, pt, c);
            const float* Pp = S->P + cp + p;
            float l = c0 * Pp[0];
            l = fmaf(c1, Pp[PSTRIDE],     l);
            l = fmaf(c2, Pp[2 * PSTRIDE], l);
            l = fmaf(c3, Pp[3 * PSTRIDE], l);
            if (p < NP) W->Ls[p] = l;
        }
        __syncwarp();

        // lm store (STG.128, coalesced) with fused out = lm @ x
        float4* lmrow = reinterpret_cast<float4*>(lm + (size_t)row * V_DIM * V_DIM);
        #pragma unroll
        for (int i = 0; i < 8; i++) {
            int t4 = lane + 32 * i;          // == v*8 + c0/4
            int v  = t4 >> 3;
            int cb = (t4 & 7) << 2;
            int pb = (v * (v - 1)) >> 1;
            float vals[4];
            #pragma unroll
            for (int q = 0; q < 4; q++) {
                int c = cb + q;
                float val = 0.0f;
                if (c < v)       val = W->Ls[pb + c];
                else if (c == v) val = 1.0f;
                vals[q] = val;
            }
            __stcs(&lmrow[t4], make_float4(vals[0], vals[1], vals[2], vals[3]));

            // dot of this v's row segment with x (8 lanes per v)
            const float4 x4 = reinterpret_cast<const float4*>(W->xs)[t4 & 7];
            float dv = vals[0] * x4.x;
            dv = fmaf(vals[1], x4.y, dv);
            dv = fmaf(vals[2], x4.z, dv);
            dv = fmaf(vals[3], x4.w, dv);
            dv += __shfl_xor_sync(0xffffffffu, dv, 4, 8);
            dv += __shfl_xor_sync(0xffffffffu, dv, 2, 8);
            dv += __shfl_xor_sync(0xffffffffu, dv, 1, 8);
            if ((lane & 7) == 0) W->Od[v] = dv;
        }
        __syncwarp();

        // coalesced out-row store
        d_out[(size_t)row * V_DIM + lane] = W->Od[lane];

        __syncwarp();   // protect scratch before next row
    }
}

extern "C" void kernel_launch(void* const* d_in, const int* in_sizes, int n_in,
                              void* d_out, int out_size)
{
    const float* input  = (const float*)d_in[0];
    // d_in[1] = log_d (unused by the reference's outputs)
    const float* params = (const float*)d_in[2];
    float* outp = (float*)d_out;
    int n = in_sizes[0] / V_DIM;

    float* scal = outp + (size_t)n * V_DIM + (size_t)n * V_DIM * V_DIM;

    size_t smem = sizeof(SmemLayout);
    cudaFuncSetAttribute(decor_kernel, cudaFuncAttributeMaxDynamicSharedMemorySize, (int)smem);

    decor_kernel<<<GRID, NTHREADS, smem>>>(input, params, outp, scal, n);
}